// round 3
// baseline (speedup 1.0000x reference)
#include <cuda_runtime.h>
#include <cstdint>

#define Bv 256
#define Tv 512
#define Iv 128
#define Hv 256
#define G4v 1024
#define REC_CTAS 128
#define MBv 32   // batch rows per CTA (8 groups)
#define HSv 16   // hidden slice per CTA (16 slices per group)

// ---------------- scratch (device globals; no cudaMalloc allowed) ----------
__device__ float g_xg[(long long)Tv * Bv * G4v];    // 512 MB gate preacts [t][b][4H]
__device__ float g_hseq[(long long)Tv * Bv * Hv];   // 128 MB layer0 output [t][b][H]
__device__ float g_hbuf[2][Bv * Hv];                // double-buffered hidden state
__device__ float g_hfinal[Bv * Hv];                 // final hidden state for FC
__device__ unsigned g_flags[8 * 32];                // per-group flag line

// ---------------- helpers ---------------------------------------------------
__device__ __forceinline__ unsigned f2tf(float f) {
    unsigned u;
    asm("cvt.rna.tf32.f32 %0, %1;" : "=r"(u) : "f"(f));
    return u;
}
__device__ __forceinline__ void mma_tf32(float c[4], unsigned a0, unsigned a1,
                                         unsigned a2, unsigned a3,
                                         unsigned b0, unsigned b1) {
    asm volatile(
        "mma.sync.aligned.m16n8k8.row.col.f32.tf32.tf32.f32 "
        "{%0,%1,%2,%3}, {%4,%5,%6,%7}, {%8,%9}, {%0,%1,%2,%3};"
        : "+f"(c[0]), "+f"(c[1]), "+f"(c[2]), "+f"(c[3])
        : "r"(a0), "r"(a1), "r"(a2), "r"(a3), "r"(b0), "r"(b1));
}
__device__ __forceinline__ float tanhfast(float x) {
    float y;
    asm("tanh.approx.f32 %0, %1;" : "=f"(y) : "f"(x));
    return y;
}
__device__ __forceinline__ float sigm(float x) {
    return fmaf(0.5f, tanhfast(0.5f * x), 0.5f);
}

// ---------------- input-projection GEMM (tf32 mma) -------------------------
__global__ void __launch_bounds__(256) gemm_tf32(
    const float* __restrict__ A_ext, int useHseq, long long sB, long long sT, int K,
    const float* __restrict__ W, const float* __restrict__ bias1,
    const float* __restrict__ bias2)
{
    __shared__ float As[128][36];
    __shared__ float Bs[64][36];

    // reset recurrence flags for the lstm_rec kernel that follows this GEMM
    if (blockIdx.x == 0 && blockIdx.y == 0 && threadIdx.x < 256)
        g_flags[threadIdx.x] = 0u;

    const float* A = useHseq ? (const float*)g_hseq : A_ext;

    int tid  = threadIdx.x;
    int lane = tid & 31, wid = tid >> 5;
    int wm = wid & 3, wn = wid >> 2;
    int mbase = wm * 32, nbase = wn * 32;
    int grp = lane >> 2, tig = lane & 3;
    int ctaN = blockIdx.x, ctaM = blockIdx.y;

    float acc[2][4][4];
#pragma unroll
    for (int a = 0; a < 2; a++)
#pragma unroll
        for (int b = 0; b < 4; b++)
#pragma unroll
            for (int c = 0; c < 4; c++) acc[a][b][c] = 0.0f;

    for (int k0 = 0; k0 < K; k0 += 32) {
#pragma unroll
        for (int i = 0; i < 4; i++) {
            int id = tid + i * 256;
            int r = id >> 3, c4 = id & 7;
            long long grow = (long long)ctaM * 128 + r;
            const float* src = A + (grow & (Bv - 1)) * sB + (grow >> 8) * sT + k0 + c4 * 4;
            float4 v = *(const float4*)src;
            As[r][c4 * 4 + 0] = __uint_as_float(f2tf(v.x));
            As[r][c4 * 4 + 1] = __uint_as_float(f2tf(v.y));
            As[r][c4 * 4 + 2] = __uint_as_float(f2tf(v.z));
            As[r][c4 * 4 + 3] = __uint_as_float(f2tf(v.w));
        }
#pragma unroll
        for (int i = 0; i < 2; i++) {
            int id = tid + i * 256;
            int r = id >> 3, c4 = id & 7;
            const float* src = W + (long long)(ctaN * 64 + r) * K + k0 + c4 * 4;
            float4 v = *(const float4*)src;
            Bs[r][c4 * 4 + 0] = __uint_as_float(f2tf(v.x));
            Bs[r][c4 * 4 + 1] = __uint_as_float(f2tf(v.y));
            Bs[r][c4 * 4 + 2] = __uint_as_float(f2tf(v.z));
            Bs[r][c4 * 4 + 3] = __uint_as_float(f2tf(v.w));
        }
        __syncthreads();

#pragma unroll
        for (int kk = 0; kk < 32; kk += 8) {
            unsigned a[2][4];
#pragma unroll
            for (int mt = 0; mt < 2; mt++) {
                int row = mbase + mt * 16 + grp;
                a[mt][0] = __float_as_uint(As[row][kk + tig]);
                a[mt][1] = __float_as_uint(As[row + 8][kk + tig]);
                a[mt][2] = __float_as_uint(As[row][kk + tig + 4]);
                a[mt][3] = __float_as_uint(As[row + 8][kk + tig + 4]);
            }
#pragma unroll
            for (int nt = 0; nt < 4; nt++) {
                int nr = nbase + nt * 8 + grp;
                unsigned b0 = __float_as_uint(Bs[nr][kk + tig]);
                unsigned b1 = __float_as_uint(Bs[nr][kk + tig + 4]);
#pragma unroll
                for (int mt = 0; mt < 2; mt++)
                    mma_tf32(acc[mt][nt], a[mt][0], a[mt][1], a[mt][2], a[mt][3], b0, b1);
            }
        }
        __syncthreads();
    }

#pragma unroll
    for (int mt = 0; mt < 2; mt++) {
#pragma unroll
        for (int nt = 0; nt < 4; nt++) {
            long long grow = (long long)ctaM * 128 + mbase + mt * 16 + grp;
            int gcol = ctaN * 64 + nbase + nt * 8 + 2 * tig;
            float bb0 = bias1[gcol] + bias2[gcol];
            float bb1 = bias1[gcol + 1] + bias2[gcol + 1];
            g_xg[grow * G4v + gcol]           = acc[mt][nt][0] + bb0;
            g_xg[grow * G4v + gcol + 1]       = acc[mt][nt][1] + bb1;
            g_xg[(grow + 8) * G4v + gcol]     = acc[mt][nt][2] + bb0;
            g_xg[(grow + 8) * G4v + gcol + 1] = acc[mt][nt][3] + bb1;
        }
    }
}

// ---------------- persistent recurrence kernel ------------------------------
// 128 CTAs: bt (8 groups of 32 batch rows) x hs (16 H-slices of 16).
// W_hh fragments live in REGISTERS (constant over time). h(t-1) staged into
// a comb-swizzled SMEM layout read with conflict-free LDS.128.
// SMEM floats: HsA 32*4*68=8704 | gates 32*68=2176 | cst 512 | slen 32 | pmax 2
__global__ void __launch_bounds__(256, 1) lstm_rec(
    const int* __restrict__ lengths, const float* __restrict__ W_hh, int writeSeq)
{
    extern __shared__ float sm[];
    float* HsA          = sm;                       // [row(32)][tig(4)][68]
    float (*gates)[68]  = (float(*)[68])(sm + 8704);
    float (*cst)[16]    = (float(*)[16])(sm + 8704 + 2176);
    int*   slen         = (int*)(sm + 8704 + 2176 + 512);
    int*   pmax         = slen + 32;

    int tid = threadIdx.x, lane = tid & 31, wid = tid >> 5;
    int bt = blockIdx.x & 7;
    int hs = blockIdx.x >> 3;
    int wm = wid & 1, wn = wid >> 1;   // 2(M) x 4(N) warps, warp tile 16x16
    int grp = lane >> 2, tig = lane & 3;
    int arow0 = wm * 16 + grp;

    // ---- load W_hh fragments into registers (tf32), constant for all steps
    // thread's B comb: rows nr(nt) = tile-n = wn*16+nt*8+grp  ->
    //   global row = wn*256 + hs*16 + nt*8 + grp ; cols k = 4u+tig, u=0..63
    unsigned Breg[2][64];
#pragma unroll
    for (int nt = 0; nt < 2; nt++) {
        const float* p = W_hh + (long long)(wn * 256 + hs * HSv + nt * 8 + grp) * Hv + tig;
#pragma unroll
        for (int u = 0; u < 64; u++)
            Breg[nt][u] = f2tf(__ldg(p + 4 * u));
    }

    if (tid < 32) slen[tid] = lengths[bt * MBv + tid];
    for (int p = tid; p < MBv * HSv; p += 256) ((float*)cst)[p] = 0.0f;
    __syncthreads();
    if (tid == 0) {
        int m = 0;
        for (int i = 0; i < 32; i++) m = max(m, slen[i]);
        pmax[0] = m;
    }
    __syncthreads();
    int maxlen = pmax[0];

    unsigned* myflag = g_flags + bt * 32 + hs;
    const unsigned* grpflags = g_flags + bt * 32;

    float hmy[2] = {0.0f, 0.0f};

    // xg prefetch registers, mapped exactly to the mma accumulator layout:
    // rows {arow0, arow0+8}, cols wn*256 + hs*16 + nt*8 + 2*tig (+1) in xg
    float2 xgp[2][2];
    {
        long long rb = (long long)(bt * MBv + arow0) * G4v;
        int cb = wn * 256 + hs * HSv + 2 * tig;
#pragma unroll
        for (int nt = 0; nt < 2; nt++) {
            xgp[nt][0] = *(const float2*)(g_xg + rb + cb + nt * 8);
            xgp[nt][1] = *(const float2*)(g_xg + rb + 8 * G4v + cb + nt * 8);
        }
    }

    for (int t = 0; t < maxlen; t++) {
        if (t > 0) {
            if (tid < 16) {
                unsigned v;
                const unsigned* fp = grpflags + tid;
                do {
                    asm volatile("ld.acquire.gpu.u32 %0, [%1];" : "=r"(v) : "l"(fp));
                } while (v < (unsigned)t);
            }
        }
        __syncthreads();   // poll done + prev iter's HsA/gates reads finished

        // stage h(t-1) into comb-swizzled HsA (tf32)
        if (t > 0) {
            const float* hb = g_hbuf[(t - 1) & 1] + (long long)bt * MBv * Hv;
#pragma unroll
            for (int i = 0; i < 8; i++) {
                int id = tid + i * 256;
                int b = id >> 6, q = id & 63;     // q = float4 col block
                float4 v = *(const float4*)(hb + b * Hv + q * 4);
                float* seg = HsA + (b * 4) * 68 + q;
                seg[0]      = __uint_as_float(f2tf(v.x));   // tig 0
                seg[68]     = __uint_as_float(f2tf(v.y));   // tig 1
                seg[136]    = __uint_as_float(f2tf(v.z));   // tig 2
                seg[204]    = __uint_as_float(f2tf(v.w));   // tig 3
            }
        }
        __syncthreads();

        // prefetch next step's xg (independent of h)
        float2 xgn[2][2];
        if (t + 1 < maxlen) {
            long long rb = ((long long)(t + 1) * Bv + bt * MBv + arow0) * G4v;
            int cb = wn * 256 + hs * HSv + 2 * tig;
#pragma unroll
            for (int nt = 0; nt < 2; nt++) {
                xgn[nt][0] = *(const float2*)(g_xg + rb + cb + nt * 8);
                xgn[nt][1] = *(const float2*)(g_xg + rb + 8 * G4v + cb + nt * 8);
            }
        }

        // acc = xg (bias already folded in by the GEMM)
        float acc[2][4];
#pragma unroll
        for (int nt = 0; nt < 2; nt++) {
            acc[nt][0] = xgp[nt][0].x;
            acc[nt][1] = xgp[nt][0].y;
            acc[nt][2] = xgp[nt][1].x;
            acc[nt][3] = xgp[nt][1].y;
        }

        if (t > 0) {
            const float4* pa = (const float4*)(HsA + (arow0 * 4 + tig) * 68);
            const float4* pb = (const float4*)(HsA + ((arow0 + 8) * 4 + tig) * 68);
#pragma unroll
            for (int j = 0; j < 16; j++) {
                float4 fa = pa[j];
                float4 fb = pb[j];
                unsigned a0 = __float_as_uint(fa.x), a1 = __float_as_uint(fb.x);
                unsigned a2 = __float_as_uint(fa.y), a3 = __float_as_uint(fb.y);
                mma_tf32(acc[0], a0, a1, a2, a3, Breg[0][4 * j], Breg[0][4 * j + 1]);
                mma_tf32(acc[1], a0, a1, a2, a3, Breg[1][4 * j], Breg[1][4 * j + 1]);
                unsigned c0 = __float_as_uint(fa.z), c1 = __float_as_uint(fb.z);
                unsigned c2 = __float_as_uint(fa.w), c3 = __float_as_uint(fb.w);
                mma_tf32(acc[0], c0, c1, c2, c3, Breg[0][4 * j + 2], Breg[0][4 * j + 3]);
                mma_tf32(acc[1], c0, c1, c2, c3, Breg[1][4 * j + 2], Breg[1][4 * j + 3]);
            }
        }
        xgp[0][0] = xgn[0][0]; xgp[0][1] = xgn[0][1];
        xgp[1][0] = xgn[1][0]; xgp[1][1] = xgn[1][1];

        // write complete gate preacts to gates tile
#pragma unroll
        for (int nt = 0; nt < 2; nt++) {
            int gc = wn * 16 + nt * 8 + 2 * tig;
            *(float2*)&gates[arow0][gc]     = make_float2(acc[nt][0], acc[nt][1]);
            *(float2*)&gates[arow0 + 8][gc] = make_float2(acc[nt][2], acc[nt][3]);
        }
        __syncthreads();

        // activations + state update (each thread: 2 (b,j) pairs)
        float* hw = g_hbuf[t & 1];
#pragma unroll
        for (int i = 0; i < 2; i++) {
            int p = tid + i * 256;
            int b = p >> 4, j = p & 15;
            bool act = (t < slen[b]);
            if (act) {
                float gi = gates[b][j];
                float gf = gates[b][16 + j];
                float gg = gates[b][32 + j];
                float go = gates[b][48 + j];
                float iv = sigm(gi), fv = sigm(gf);
                float gv = tanhfast(gg), ov = sigm(go);
                float cn = fv * cst[b][j] + iv * gv;
                cst[b][j] = cn;
                hmy[i] = ov * tanhfast(cn);
            }
            hw[(long long)(bt * MBv + b) * Hv + hs * HSv + j] = hmy[i];
            if (writeSeq && act)
                g_hseq[((long long)t * Bv + bt * MBv + b) * Hv + hs * HSv + j] = hmy[i];
        }

        __syncthreads();
        if (tid == 0) {
            unsigned nv = (unsigned)(t + 1);
            asm volatile("st.release.gpu.u32 [%0], %1;" :: "l"(myflag), "r"(nv) : "memory");
        }
    }

    // publish final hidden state for FC
#pragma unroll
    for (int i = 0; i < 2; i++) {
        int p = tid + i * 256;
        int b = p >> 4, j = p & 15;
        g_hfinal[(long long)(bt * MBv + b) * Hv + hs * HSv + j] = hmy[i];
    }
}

// ---------------- final FC + softmax ----------------------------------------
__global__ void fc_softmax(const float* __restrict__ W_fc,
                           const float* __restrict__ b_fc, float* __restrict__ out)
{
    int b = blockIdx.x, lane = threadIdx.x;
    float logit[10];
#pragma unroll
    for (int c = 0; c < 10; c++) {
        float s = 0.0f;
        for (int h = lane; h < Hv; h += 32)
            s += g_hfinal[b * Hv + h] * W_fc[c * Hv + h];
#pragma unroll
        for (int o = 16; o; o >>= 1) s += __shfl_down_sync(0xffffffffu, s, o);
        logit[c] = s;
    }
    if (lane == 0) {
        float mx = -1e30f;
#pragma unroll
        for (int c = 0; c < 10; c++) {
            logit[c] += b_fc[c];
            mx = fmaxf(mx, logit[c]);
        }
        float sum = 0.0f;
#pragma unroll
        for (int c = 0; c < 10; c++) {
            logit[c] = expf(logit[c] - mx);
            sum += logit[c];
        }
        float inv = 1.0f / sum;
#pragma unroll
        for (int c = 0; c < 10; c++) out[b * 10 + c] = logit[c] * inv;
    }
}

// ---------------- host launcher ---------------------------------------------
extern "C" void kernel_launch(void* const* d_in, const int* in_sizes, int n_in,
                              void* d_out, int out_size)
{
    const float* x      = (const float*)d_in[0];
    const int*   length = (const int*)d_in[1];
    const float* W_fc   = (const float*)d_in[2];
    const float* b_fc   = (const float*)d_in[3];
    const float* W_ih0  = (const float*)d_in[4];
    const float* W_hh0  = (const float*)d_in[5];
    const float* b_ih0  = (const float*)d_in[6];
    const float* b_hh0  = (const float*)d_in[7];
    const float* W_ih1  = (const float*)d_in[8];
    const float* W_hh1  = (const float*)d_in[9];
    const float* b_ih1  = (const float*)d_in[10];
    const float* b_hh1  = (const float*)d_in[11];
    float* out = (float*)d_out;

    int smem = (8704 + 2176 + 512 + 34) * 4;
    cudaFuncSetAttribute(lstm_rec, cudaFuncAttributeMaxDynamicSharedMemorySize, smem);

    dim3 ggrid(G4v / 64, (Tv * Bv) / 128);

    // layer 0 input projection: Xg = X @ W_ih0^T + (b_ih0 + b_hh0)
    gemm_tf32<<<ggrid, 256>>>(x, 0, (long long)Tv * Iv, (long long)Iv, Iv,
                              W_ih0, b_ih0, b_hh0);
    // layer 0 recurrence (writes g_hseq)
    lstm_rec<<<REC_CTAS, 256, smem>>>(length, W_hh0, 1);
    // layer 1 input projection: Xg = hseq @ W_ih1^T + (b_ih1 + b_hh1)
    gemm_tf32<<<ggrid, 256>>>(nullptr, 1, (long long)Hv, (long long)Bv * Hv, Hv,
                              W_ih1, b_ih1, b_hh1);
    // layer 1 recurrence (final h -> g_hfinal)
    lstm_rec<<<REC_CTAS, 256, smem>>>(length, W_hh1, 0);
    // FC + softmax
    fc_softmax<<<Bv, 32>>>(W_fc, b_fc, out);
}

// round 4
// speedup vs baseline: 1.3407x; 1.3407x over previous
#include <cuda_runtime.h>
#include <cstdint>

#define Bv 256
#define Tv 512
#define Iv 128
#define Hv 256
#define G4v 1024
#define REC_CTAS 128
#define MBv 32   // batch rows per CTA (8 groups)
#define HSv 16   // hidden slice per CTA (16 slices per group)

// ---------------- scratch (device globals; no cudaMalloc allowed) ----------
__device__ float g_xg[(long long)Tv * Bv * G4v];    // 512 MB gate preacts [t][b][4H]
__device__ float g_hseq[(long long)Tv * Bv * Hv];   // 128 MB layer0 output [t][b][H]
__device__ float g_hbuf[2][Bv * Hv];                // double-buffered hidden state
__device__ float g_hfinal[Bv * Hv];                 // final hidden state for FC
__device__ unsigned g_flags[8 * 32];                // per-group flag line

// ---------------- helpers ---------------------------------------------------
__device__ __forceinline__ unsigned f2tf(float f) {
    unsigned u;
    asm("cvt.rna.tf32.f32 %0, %1;" : "=r"(u) : "f"(f));
    return u;
}
__device__ __forceinline__ void mma_tf32(float c[4], unsigned a0, unsigned a1,
                                         unsigned a2, unsigned a3,
                                         unsigned b0, unsigned b1) {
    asm volatile(
        "mma.sync.aligned.m16n8k8.row.col.f32.tf32.tf32.f32 "
        "{%0,%1,%2,%3}, {%4,%5,%6,%7}, {%8,%9}, {%0,%1,%2,%3};"
        : "+f"(c[0]), "+f"(c[1]), "+f"(c[2]), "+f"(c[3])
        : "r"(a0), "r"(a1), "r"(a2), "r"(a3), "r"(b0), "r"(b1));
}
__device__ __forceinline__ float tanhfast(float x) {
    float y;
    asm("tanh.approx.f32 %0, %1;" : "=f"(y) : "f"(x));
    return y;
}
__device__ __forceinline__ float sigm(float x) {
    return fmaf(0.5f, tanhfast(0.5f * x), 0.5f);
}

// ---------------- input-projection GEMM (tf32 mma) -------------------------
__global__ void __launch_bounds__(256) gemm_tf32(
    const float* __restrict__ A_ext, int useHseq, long long sB, long long sT, int K,
    const float* __restrict__ W, const float* __restrict__ bias1,
    const float* __restrict__ bias2)
{
    __shared__ float As[128][36];
    __shared__ float Bs[64][36];

    // reset recurrence flags for the lstm_rec kernel that follows this GEMM
    if (blockIdx.x == 0 && blockIdx.y == 0 && threadIdx.x < 256)
        g_flags[threadIdx.x] = 0u;

    const float* A = useHseq ? (const float*)g_hseq : A_ext;

    int tid  = threadIdx.x;
    int lane = tid & 31, wid = tid >> 5;
    int wm = wid & 3, wn = wid >> 2;
    int mbase = wm * 32, nbase = wn * 32;
    int grp = lane >> 2, tig = lane & 3;
    int ctaN = blockIdx.x, ctaM = blockIdx.y;

    float acc[2][4][4];
#pragma unroll
    for (int a = 0; a < 2; a++)
#pragma unroll
        for (int b = 0; b < 4; b++)
#pragma unroll
            for (int c = 0; c < 4; c++) acc[a][b][c] = 0.0f;

    for (int k0 = 0; k0 < K; k0 += 32) {
#pragma unroll
        for (int i = 0; i < 4; i++) {
            int id = tid + i * 256;
            int r = id >> 3, c4 = id & 7;
            long long grow = (long long)ctaM * 128 + r;
            const float* src = A + (grow & (Bv - 1)) * sB + (grow >> 8) * sT + k0 + c4 * 4;
            float4 v = *(const float4*)src;
            As[r][c4 * 4 + 0] = __uint_as_float(f2tf(v.x));
            As[r][c4 * 4 + 1] = __uint_as_float(f2tf(v.y));
            As[r][c4 * 4 + 2] = __uint_as_float(f2tf(v.z));
            As[r][c4 * 4 + 3] = __uint_as_float(f2tf(v.w));
        }
#pragma unroll
        for (int i = 0; i < 2; i++) {
            int id = tid + i * 256;
            int r = id >> 3, c4 = id & 7;
            const float* src = W + (long long)(ctaN * 64 + r) * K + k0 + c4 * 4;
            float4 v = *(const float4*)src;
            Bs[r][c4 * 4 + 0] = __uint_as_float(f2tf(v.x));
            Bs[r][c4 * 4 + 1] = __uint_as_float(f2tf(v.y));
            Bs[r][c4 * 4 + 2] = __uint_as_float(f2tf(v.z));
            Bs[r][c4 * 4 + 3] = __uint_as_float(f2tf(v.w));
        }
        __syncthreads();

#pragma unroll
        for (int kk = 0; kk < 32; kk += 8) {
            unsigned a[2][4];
#pragma unroll
            for (int mt = 0; mt < 2; mt++) {
                int row = mbase + mt * 16 + grp;
                a[mt][0] = __float_as_uint(As[row][kk + tig]);
                a[mt][1] = __float_as_uint(As[row + 8][kk + tig]);
                a[mt][2] = __float_as_uint(As[row][kk + tig + 4]);
                a[mt][3] = __float_as_uint(As[row + 8][kk + tig + 4]);
            }
#pragma unroll
            for (int nt = 0; nt < 4; nt++) {
                int nr = nbase + nt * 8 + grp;
                unsigned b0 = __float_as_uint(Bs[nr][kk + tig]);
                unsigned b1 = __float_as_uint(Bs[nr][kk + tig + 4]);
#pragma unroll
                for (int mt = 0; mt < 2; mt++)
                    mma_tf32(acc[mt][nt], a[mt][0], a[mt][1], a[mt][2], a[mt][3], b0, b1);
            }
        }
        __syncthreads();
    }

#pragma unroll
    for (int mt = 0; mt < 2; mt++) {
#pragma unroll
        for (int nt = 0; nt < 4; nt++) {
            long long grow = (long long)ctaM * 128 + mbase + mt * 16 + grp;
            int gcol = ctaN * 64 + nbase + nt * 8 + 2 * tig;
            float bb0 = bias1[gcol] + bias2[gcol];
            float bb1 = bias1[gcol + 1] + bias2[gcol + 1];
            g_xg[grow * G4v + gcol]           = acc[mt][nt][0] + bb0;
            g_xg[grow * G4v + gcol + 1]       = acc[mt][nt][1] + bb1;
            g_xg[(grow + 8) * G4v + gcol]     = acc[mt][nt][2] + bb0;
            g_xg[(grow + 8) * G4v + gcol + 1] = acc[mt][nt][3] + bb1;
        }
    }
}

// ---------------- persistent recurrence kernel ------------------------------
// 128 CTAs: bt (8 groups of 32 batch rows) x hs (16 H-slices of 16).
// W_hh fragments in registers; h staged comb-swizzled for LDS.128;
// split accumulator chains; early flag release; hseq stores after release.
__global__ void __launch_bounds__(256, 1) lstm_rec(
    const int* __restrict__ lengths, const float* __restrict__ W_hh, int writeSeq)
{
    extern __shared__ float sm[];
    float* HsA          = sm;                       // [row(32)][tig(4)][68]
    float (*gates)[68]  = (float(*)[68])(sm + 8704);
    float* cst          = sm + 8704 + 2176;         // [32][16]
    int*   slen         = (int*)(sm + 8704 + 2176 + 512);
    int*   pmax         = slen + 32;

    int tid = threadIdx.x, lane = tid & 31, wid = tid >> 5;
    int bt = blockIdx.x & 7;
    int hs = blockIdx.x >> 3;
    int wm = wid & 1, wn = wid >> 1;   // 2(M) x 4(N) warps, warp tile 16x16
    int grp = lane >> 2, tig = lane & 3;
    int arow0 = wm * 16 + grp;

    // ---- load W_hh fragments into registers (tf32), constant for all steps
    unsigned Breg[2][64];
#pragma unroll
    for (int nt = 0; nt < 2; nt++) {
        const float* p = W_hh + (long long)(wn * 256 + hs * HSv + nt * 8 + grp) * Hv + tig;
#pragma unroll
        for (int u = 0; u < 64; u++)
            Breg[nt][u] = f2tf(__ldg(p + 4 * u));
    }

    if (tid < 32) slen[tid] = lengths[bt * MBv + tid];
    for (int p = tid; p < MBv * HSv; p += 256) cst[p] = 0.0f;
    __syncthreads();
    if (tid == 0) {
        int m = 0;
        for (int i = 0; i < 32; i++) m = max(m, slen[i]);
        pmax[0] = m;
    }
    __syncthreads();
    int maxlen = pmax[0];

    unsigned* myflag = g_flags + bt * 32 + hs;
    const unsigned* grpflags = g_flags + bt * 32;

    // epilogue mapping: this thread owns (eb, ej..ej+1)
    int eb = tid >> 3;           // 0..31
    int ej = (tid & 7) * 2;      // 0,2,...,14
    int mylen = slen[eb];
    float2 hmy = make_float2(0.0f, 0.0f);

    // xg prefetch registers (mma accumulator layout)
    float2 xgp[2][2];
    {
        long long rb = (long long)(bt * MBv + arow0) * G4v;
        int cb = wn * 256 + hs * HSv + 2 * tig;
#pragma unroll
        for (int nt = 0; nt < 2; nt++) {
            xgp[nt][0] = *(const float2*)(g_xg + rb + cb + nt * 8);
            xgp[nt][1] = *(const float2*)(g_xg + rb + 8 * G4v + cb + nt * 8);
        }
    }

    for (int t = 0; t < maxlen; t++) {
        // ---- 1. issue xg prefetch for t+1 FIRST (depends on nothing)
        float2 xgn[2][2];
        if (t + 1 < maxlen) {
            long long rb = ((long long)(t + 1) * Bv + bt * MBv + arow0) * G4v;
            int cb = wn * 256 + hs * HSv + 2 * tig;
#pragma unroll
            for (int nt = 0; nt < 2; nt++) {
                xgn[nt][0] = *(const float2*)(g_xg + rb + cb + nt * 8);
                xgn[nt][1] = *(const float2*)(g_xg + rb + 8 * G4v + cb + nt * 8);
            }
        }

        // ---- 2. wait for group peers to complete step t-1
        if (t > 0) {
            if (tid < 16) {
                const unsigned* fp = grpflags + tid;
                unsigned v;
                asm volatile("ld.acquire.gpu.u32 %0, [%1];" : "=r"(v) : "l"(fp));
                while (v < (unsigned)t) {
                    __nanosleep(40);
                    asm volatile("ld.acquire.gpu.u32 %0, [%1];" : "=r"(v) : "l"(fp));
                }
            }
        }
        __syncthreads();

        // ---- 3. stage h(t-1) into comb-swizzled HsA (tf32)
        if (t > 0) {
            const float* hb = g_hbuf[(t - 1) & 1] + (long long)bt * MBv * Hv;
#pragma unroll
            for (int i = 0; i < 8; i++) {
                int id = tid + i * 256;
                int b = id >> 6, q = id & 63;
                float4 v = *(const float4*)(hb + b * Hv + q * 4);
                float* seg = HsA + (b * 4) * 68 + q;
                seg[0]   = __uint_as_float(f2tf(v.x));
                seg[68]  = __uint_as_float(f2tf(v.y));
                seg[136] = __uint_as_float(f2tf(v.z));
                seg[204] = __uint_as_float(f2tf(v.w));
            }
        }
        __syncthreads();

        // ---- 4. mma with 2-way split accumulator chains
        float accA[2][4], accB[2][4];
#pragma unroll
        for (int nt = 0; nt < 2; nt++) {
            accA[nt][0] = xgp[nt][0].x;
            accA[nt][1] = xgp[nt][0].y;
            accA[nt][2] = xgp[nt][1].x;
            accA[nt][3] = xgp[nt][1].y;
            accB[nt][0] = 0.0f; accB[nt][1] = 0.0f;
            accB[nt][2] = 0.0f; accB[nt][3] = 0.0f;
        }

        if (t > 0) {
            const float4* pa = (const float4*)(HsA + (arow0 * 4 + tig) * 68);
            const float4* pb = (const float4*)(HsA + ((arow0 + 8) * 4 + tig) * 68);
#pragma unroll
            for (int j = 0; j < 16; j++) {
                float4 fa = pa[j];
                float4 fb = pb[j];
                unsigned a0 = __float_as_uint(fa.x), a1 = __float_as_uint(fb.x);
                unsigned a2 = __float_as_uint(fa.y), a3 = __float_as_uint(fb.y);
                mma_tf32(accA[0], a0, a1, a2, a3, Breg[0][4 * j], Breg[0][4 * j + 1]);
                mma_tf32(accA[1], a0, a1, a2, a3, Breg[1][4 * j], Breg[1][4 * j + 1]);
                unsigned c0 = __float_as_uint(fa.z), c1 = __float_as_uint(fb.z);
                unsigned c2 = __float_as_uint(fa.w), c3 = __float_as_uint(fb.w);
                mma_tf32(accB[0], c0, c1, c2, c3, Breg[0][4 * j + 2], Breg[0][4 * j + 3]);
                mma_tf32(accB[1], c0, c1, c2, c3, Breg[1][4 * j + 2], Breg[1][4 * j + 3]);
            }
        }
        xgp[0][0] = xgn[0][0]; xgp[0][1] = xgn[0][1];
        xgp[1][0] = xgn[1][0]; xgp[1][1] = xgn[1][1];

        // ---- 5. write complete gate preacts
#pragma unroll
        for (int nt = 0; nt < 2; nt++) {
            int gc = wn * 16 + nt * 8 + 2 * tig;
            *(float2*)&gates[arow0][gc] =
                make_float2(accA[nt][0] + accB[nt][0], accA[nt][1] + accB[nt][1]);
            *(float2*)&gates[arow0 + 8][gc] =
                make_float2(accA[nt][2] + accB[nt][2], accA[nt][3] + accB[nt][3]);
        }
        __syncthreads();

        // ---- 6. activations + state update (thread owns (eb, ej..ej+1))
        bool act = (t < mylen);
        if (act) {
            float2 gi = *(const float2*)&gates[eb][ej];
            float2 gf = *(const float2*)&gates[eb][16 + ej];
            float2 gg = *(const float2*)&gates[eb][32 + ej];
            float2 go = *(const float2*)&gates[eb][48 + ej];
            float2 cv = *(const float2*)&cst[eb * 16 + ej];
            float i0 = sigm(gi.x), i1 = sigm(gi.y);
            float f0 = sigm(gf.x), f1 = sigm(gf.y);
            float g0 = tanhfast(gg.x), g1 = tanhfast(gg.y);
            float o0 = sigm(go.x), o1 = sigm(go.y);
            float cn0 = fmaf(f0, cv.x, i0 * g0);
            float cn1 = fmaf(f1, cv.y, i1 * g1);
            *(float2*)&cst[eb * 16 + ej] = make_float2(cn0, cn1);
            hmy = make_float2(o0 * tanhfast(cn0), o1 * tanhfast(cn1));
        }
        *(float2*)(g_hbuf[t & 1] + (long long)(bt * MBv + eb) * Hv + hs * HSv + ej) = hmy;

        __syncthreads();   // all hbuf stores performed (write-through to L2)

        // ---- 7. EARLY release, then (unordered) hseq store
        if (tid == 0) {
            unsigned nv = (unsigned)(t + 1);
            asm volatile("st.release.gpu.u32 [%0], %1;" :: "l"(myflag), "r"(nv) : "memory");
        }
        if (writeSeq && act)
            *(float2*)(g_hseq + ((long long)t * Bv + bt * MBv + eb) * Hv + hs * HSv + ej) = hmy;
    }

    // publish final hidden state for FC
    *(float2*)(g_hfinal + (long long)(bt * MBv + eb) * Hv + hs * HSv + ej) = hmy;
}

// ---------------- final FC + softmax ----------------------------------------
__global__ void fc_softmax(const float* __restrict__ W_fc,
                           const float* __restrict__ b_fc, float* __restrict__ out)
{
    int b = blockIdx.x, lane = threadIdx.x;
    float logit[10];
#pragma unroll
    for (int c = 0; c < 10; c++) {
        float s = 0.0f;
        for (int h = lane; h < Hv; h += 32)
            s += g_hfinal[b * Hv + h] * W_fc[c * Hv + h];
#pragma unroll
        for (int o = 16; o; o >>= 1) s += __shfl_down_sync(0xffffffffu, s, o);
        logit[c] = s;
    }
    if (lane == 0) {
        float mx = -1e30f;
#pragma unroll
        for (int c = 0; c < 10; c++) {
            logit[c] += b_fc[c];
            mx = fmaxf(mx, logit[c]);
        }
        float sum = 0.0f;
#pragma unroll
        for (int c = 0; c < 10; c++) {
            logit[c] = expf(logit[c] - mx);
            sum += logit[c];
        }
        float inv = 1.0f / sum;
#pragma unroll
        for (int c = 0; c < 10; c++) out[b * 10 + c] = logit[c] * inv;
    }
}

// ---------------- host launcher ---------------------------------------------
extern "C" void kernel_launch(void* const* d_in, const int* in_sizes, int n_in,
                              void* d_out, int out_size)
{
    const float* x      = (const float*)d_in[0];
    const int*   length = (const int*)d_in[1];
    const float* W_fc   = (const float*)d_in[2];
    const float* b_fc   = (const float*)d_in[3];
    const float* W_ih0  = (const float*)d_in[4];
    const float* W_hh0  = (const float*)d_in[5];
    const float* b_ih0  = (const float*)d_in[6];
    const float* b_hh0  = (const float*)d_in[7];
    const float* W_ih1  = (const float*)d_in[8];
    const float* W_hh1  = (const float*)d_in[9];
    const float* b_ih1  = (const float*)d_in[10];
    const float* b_hh1  = (const float*)d_in[11];
    float* out = (float*)d_out;

    int smem = (8704 + 2176 + 512 + 34) * 4;
    cudaFuncSetAttribute(lstm_rec, cudaFuncAttributeMaxDynamicSharedMemorySize, smem);

    dim3 ggrid(G4v / 64, (Tv * Bv) / 128);

    // layer 0 input projection: Xg = X @ W_ih0^T + (b_ih0 + b_hh0)
    gemm_tf32<<<ggrid, 256>>>(x, 0, (long long)Tv * Iv, (long long)Iv, Iv,
                              W_ih0, b_ih0, b_hh0);
    // layer 0 recurrence (writes g_hseq)
    lstm_rec<<<REC_CTAS, 256, smem>>>(length, W_hh0, 1);
    // layer 1 input projection: Xg = hseq @ W_ih1^T + (b_ih1 + b_hh1)
    gemm_tf32<<<ggrid, 256>>>(nullptr, 1, (long long)Hv, (long long)Bv * Hv, Hv,
                              W_ih1, b_ih1, b_hh1);
    // layer 1 recurrence (final h -> g_hfinal)
    lstm_rec<<<REC_CTAS, 256, smem>>>(length, W_hh1, 0);
    // FC + softmax
    fc_softmax<<<Bv, 32>>>(W_fc, b_fc, out);
}